// round 1
// baseline (speedup 1.0000x reference)
#include <cuda_runtime.h>
#include <cuda_bf16.h>
#include <math.h>

// Problem constants
#define BB 4
#define TT 2048
#define CC 1024
#define NHH 16
#define HDD 64
#define ROWS (BB*TT)          // 8192
#define N_QKV (3*CC)          // 3072

// ---------------- scratch (device globals; no allocation) ----------------
__device__ float g_qkv[(size_t)ROWS * N_QKV];          // [8192][3072]
__device__ float g_q[(size_t)BB * NHH * TT * HDD];     // [b,h,t,d]
__device__ float g_k[(size_t)BB * NHH * TT * HDD];
__device__ float g_v[(size_t)BB * NHH * TT * HDD];
__device__ float g_y[(size_t)ROWS * CC];               // attention out, [b,t,c]

// ---------------- SGEMM: C = A[MxK] @ B[KxN] + bias[N] -------------------
// BM=BN=128, BK=16, 256 threads, 8x8 per thread. All dims divisible.
__global__ __launch_bounds__(256) void sgemm_bias_kernel(
    const float* __restrict__ A, const float* __restrict__ Bm,
    const float* __restrict__ bias, float* __restrict__ C,
    int M, int N, int K)
{
    __shared__ float sA[16][132];   // transposed A tile: sA[k][row]
    __shared__ float sB[16][128];

    const int tid = threadIdx.x;
    const int row0 = blockIdx.y * 128;
    const int col0 = blockIdx.x * 128;
    const int rowBase = (tid >> 4) << 3;   // (tid/16)*8
    const int colBase = (tid & 15) << 3;   // (tid%16)*8

    float acc[8][8];
    #pragma unroll
    for (int i = 0; i < 8; i++)
        #pragma unroll
        for (int j = 0; j < 8; j++) acc[i][j] = 0.f;

    for (int k0 = 0; k0 < K; k0 += 16) {
        // load A tile 128x16 (transposed into smem)
        #pragma unroll
        for (int r = 0; r < 2; r++) {
            int idx = tid + r * 256;           // 0..511 float4s
            int arow = idx >> 2;               // 0..127
            int akq = (idx & 3) << 2;          // 0,4,8,12
            float4 v = *(const float4*)&A[(size_t)(row0 + arow) * K + k0 + akq];
            sA[akq + 0][arow] = v.x;
            sA[akq + 1][arow] = v.y;
            sA[akq + 2][arow] = v.z;
            sA[akq + 3][arow] = v.w;
        }
        // load B tile 16x128
        #pragma unroll
        for (int r = 0; r < 2; r++) {
            int idx = tid + r * 256;
            int brow = idx >> 5;               // 0..15
            int bc = (idx & 31) << 2;          // 0..124
            *(float4*)&sB[brow][bc] =
                *(const float4*)&Bm[(size_t)(k0 + brow) * N + col0 + bc];
        }
        __syncthreads();

        #pragma unroll
        for (int k = 0; k < 16; k++) {
            float a[8], b[8];
            *(float4*)&a[0] = *(const float4*)&sA[k][rowBase];
            *(float4*)&a[4] = *(const float4*)&sA[k][rowBase + 4];
            *(float4*)&b[0] = *(const float4*)&sB[k][colBase];
            *(float4*)&b[4] = *(const float4*)&sB[k][colBase + 4];
            #pragma unroll
            for (int i = 0; i < 8; i++)
                #pragma unroll
                for (int j = 0; j < 8; j++)
                    acc[i][j] += a[i] * b[j];
        }
        __syncthreads();
    }

    // epilogue with bias
    #pragma unroll
    for (int i = 0; i < 8; i++) {
        #pragma unroll
        for (int j4 = 0; j4 < 8; j4 += 4) {
            float4 o;
            o.x = acc[i][j4 + 0] + bias[col0 + colBase + j4 + 0];
            o.y = acc[i][j4 + 1] + bias[col0 + colBase + j4 + 1];
            o.z = acc[i][j4 + 2] + bias[col0 + colBase + j4 + 2];
            o.w = acc[i][j4 + 3] + bias[col0 + colBase + j4 + 3];
            *(float4*)&C[(size_t)(row0 + rowBase + i) * N + col0 + colBase + j4] = o;
        }
    }
}

// ---------------- RoPE + head split --------------------------------------
// idx = ((b*NH + h)*T + t)*HD + d  (matches [b,h,t,d] output layout)
__global__ __launch_bounds__(256) void rope_split_kernel(
    const float* __restrict__ qkv,
    float* __restrict__ Q, float* __restrict__ Kh, float* __restrict__ V)
{
    int idx = blockIdx.x * 256 + threadIdx.x;
    int d = idx & 63;
    int t = (idx >> 6) & 2047;
    int h = (idx >> 17) & 15;
    int b = idx >> 21;

    size_t rowoff = ((size_t)b * TT + t) * N_QKV;
    int colq = h * HDD + d;

    float uq = qkv[rowoff + colq];
    float uk = qkv[rowoff + CC + colq];
    float uv = qkv[rowoff + 2 * CC + colq];

    bool hi = d >= 32;
    int i = d & 31;
    // inv_freq = 10000^(-i/32), computed in double for accuracy
    double inv = exp(-(double)i / 32.0 * 9.210340371976184);  // ln(10000)
    double fr = (double)t * inv;
    double sv, cv;
    sincos(fr, &sv, &cv);
    float cosv = (float)cv, sinv = (float)sv;

    int pcol = hi ? (colq - 32) : (colq + 32);
    float pq = qkv[rowoff + pcol];
    float pk = qkv[rowoff + CC + pcol];
    float rq = hi ? pq : -pq;
    float rk = hi ? pk : -pk;

    Q[idx] = uq * cosv + rq * sinv;
    Kh[idx] = uk * cosv + rk * sinv;
    V[idx] = uv;
}

// ---------------- Flash attention (causal, fp32) --------------------------
// BM=BN=64, HD=64, 256 threads (16x16), each thread a 4x4 tile.
#define QK_LD 72   // stride for QsT/KsT [d][row], float4-aligned
#define PV_LD 68   // stride for Vs/Ps, float4-aligned

__global__ __launch_bounds__(256) void flash_attn_kernel(
    const float* __restrict__ Qg, const float* __restrict__ Kg,
    const float* __restrict__ Vg, float* __restrict__ Yg)
{
    extern __shared__ float sm[];
    float* QsT = sm;                         // [64][QK_LD], d-major
    float* KsT = QsT + 64 * QK_LD;           // [64][QK_LD], d-major
    float* Vs  = KsT + 64 * QK_LD;           // [64][PV_LD], row-major
    float* Ps  = Vs  + 64 * PV_LD;           // [64][PV_LD]

    const int tid = threadIdx.x;
    const int ty = tid >> 4;                 // 0..15 -> 4 S rows
    const int tx = tid & 15;                 // 0..15 -> 4 S cols
    const int qtile = blockIdx.x;            // 0..31
    const int bh = blockIdx.y;               // 0..63
    const int b = bh >> 4, h = bh & 15;

    const float* Qb = Qg + ((size_t)bh * TT + qtile * 64) * HDD;

    // load Q tile transposed
    #pragma unroll
    for (int r = 0; r < 4; r++) {
        int idx = tid + r * 256;
        int trow = idx >> 4;
        int dg = (idx & 15) << 2;
        float4 v = *(const float4*)(Qb + trow * 64 + dg);
        QsT[(dg + 0) * QK_LD + trow] = v.x;
        QsT[(dg + 1) * QK_LD + trow] = v.y;
        QsT[(dg + 2) * QK_LD + trow] = v.z;
        QsT[(dg + 3) * QK_LD + trow] = v.w;
    }

    float m[4], l[4], acc[4][4];
    #pragma unroll
    for (int i = 0; i < 4; i++) {
        m[i] = -1e30f; l[i] = 0.f;
        #pragma unroll
        for (int j = 0; j < 4; j++) acc[i][j] = 0.f;
    }
    __syncthreads();

    for (int kt = 0; kt <= qtile; kt++) {
        const float* Kb = Kg + ((size_t)bh * TT + kt * 64) * HDD;
        const float* Vb = Vg + ((size_t)bh * TT + kt * 64) * HDD;
        #pragma unroll
        for (int r = 0; r < 4; r++) {
            int idx = tid + r * 256;
            int trow = idx >> 4;
            int dg = (idx & 15) << 2;
            float4 v = *(const float4*)(Kb + trow * 64 + dg);
            KsT[(dg + 0) * QK_LD + trow] = v.x;
            KsT[(dg + 1) * QK_LD + trow] = v.y;
            KsT[(dg + 2) * QK_LD + trow] = v.z;
            KsT[(dg + 3) * QK_LD + trow] = v.w;
            float4 w = *(const float4*)(Vb + trow * 64 + dg);
            *(float4*)(Vs + trow * PV_LD + dg) = w;
        }
        __syncthreads();

        // S = Q K^T
        float s[4][4];
        #pragma unroll
        for (int i = 0; i < 4; i++)
            #pragma unroll
            for (int j = 0; j < 4; j++) s[i][j] = 0.f;

        #pragma unroll 8
        for (int k = 0; k < 64; k++) {
            float4 qv = *(const float4*)(QsT + k * QK_LD + (ty << 2));
            float4 kv = *(const float4*)(KsT + k * QK_LD + (tx << 2));
            s[0][0] += qv.x * kv.x; s[0][1] += qv.x * kv.y; s[0][2] += qv.x * kv.z; s[0][3] += qv.x * kv.w;
            s[1][0] += qv.y * kv.x; s[1][1] += qv.y * kv.y; s[1][2] += qv.y * kv.z; s[1][3] += qv.y * kv.w;
            s[2][0] += qv.z * kv.x; s[2][1] += qv.z * kv.y; s[2][2] += qv.z * kv.z; s[2][3] += qv.z * kv.w;
            s[3][0] += qv.w * kv.x; s[3][1] += qv.w * kv.y; s[3][2] += qv.w * kv.z; s[3][3] += qv.w * kv.w;
        }

        // scale + causal mask (only diagonal tile needs masking)
        const float sc = 0.125f;  // 1/sqrt(64)
        if (kt == qtile) {
            #pragma unroll
            for (int i = 0; i < 4; i++)
                #pragma unroll
                for (int j = 0; j < 4; j++) {
                    int rr = (ty << 2) + i, cc = (tx << 2) + j;
                    s[i][j] = (cc <= rr) ? s[i][j] * sc : -1e30f;
                }
        } else {
            #pragma unroll
            for (int i = 0; i < 4; i++)
                #pragma unroll
                for (int j = 0; j < 4; j++) s[i][j] *= sc;
        }

        // online softmax
        #pragma unroll
        for (int i = 0; i < 4; i++) {
            float mx = fmaxf(fmaxf(s[i][0], s[i][1]), fmaxf(s[i][2], s[i][3]));
            #pragma unroll
            for (int o = 8; o > 0; o >>= 1)
                mx = fmaxf(mx, __shfl_xor_sync(0xffffffffu, mx, o));
            float mnew = fmaxf(m[i], mx);
            float alpha = __expf(m[i] - mnew);
            float rs = 0.f;
            #pragma unroll
            for (int j = 0; j < 4; j++) {
                float p = __expf(s[i][j] - mnew);
                s[i][j] = p;
                rs += p;
            }
            #pragma unroll
            for (int o = 8; o > 0; o >>= 1)
                rs += __shfl_xor_sync(0xffffffffu, rs, o);
            l[i] = l[i] * alpha + rs;
            m[i] = mnew;
            acc[i][0] *= alpha; acc[i][1] *= alpha; acc[i][2] *= alpha; acc[i][3] *= alpha;
        }

        // store P to smem
        #pragma unroll
        for (int i = 0; i < 4; i++) {
            float4 pv = make_float4(s[i][0], s[i][1], s[i][2], s[i][3]);
            *(float4*)(Ps + (((ty << 2) + i) * PV_LD) + (tx << 2)) = pv;
        }
        __syncthreads();

        // O += P @ V
        #pragma unroll 8
        for (int c = 0; c < 64; c++) {
            float4 vv = *(const float4*)(Vs + c * PV_LD + (tx << 2));
            float p0 = Ps[((ty << 2) + 0) * PV_LD + c];
            float p1 = Ps[((ty << 2) + 1) * PV_LD + c];
            float p2 = Ps[((ty << 2) + 2) * PV_LD + c];
            float p3 = Ps[((ty << 2) + 3) * PV_LD + c];
            acc[0][0] += p0 * vv.x; acc[0][1] += p0 * vv.y; acc[0][2] += p0 * vv.z; acc[0][3] += p0 * vv.w;
            acc[1][0] += p1 * vv.x; acc[1][1] += p1 * vv.y; acc[1][2] += p1 * vv.z; acc[1][3] += p1 * vv.w;
            acc[2][0] += p2 * vv.x; acc[2][1] += p2 * vv.y; acc[2][2] += p2 * vv.z; acc[2][3] += p2 * vv.w;
            acc[3][0] += p3 * vv.x; acc[3][1] += p3 * vv.y; acc[3][2] += p3 * vv.z; acc[3][3] += p3 * vv.w;
        }
        __syncthreads();
    }

    // write back to [b,t,c]
    #pragma unroll
    for (int i = 0; i < 4; i++) {
        float inv = 1.f / l[i];
        int tglob = qtile * 64 + (ty << 2) + i;
        float4 o = make_float4(acc[i][0] * inv, acc[i][1] * inv,
                               acc[i][2] * inv, acc[i][3] * inv);
        *(float4*)(Yg + ((size_t)(b * TT + tglob)) * CC + h * HDD + (tx << 2)) = o;
    }
}

// ---------------- launch ---------------------------------------------------
extern "C" void kernel_launch(void* const* d_in, const int* in_sizes, int n_in,
                              void* d_out, int out_size)
{
    const float* x     = (const float*)d_in[0];
    const float* Wqkv  = (const float*)d_in[1];
    const float* bqkv  = (const float*)d_in[2];
    const float* Wproj = (const float*)d_in[3];
    const float* bproj = (const float*)d_in[4];
    float* out = (float*)d_out;

    float *qkv, *Q, *K, *V, *Y;
    cudaGetSymbolAddress((void**)&qkv, g_qkv);
    cudaGetSymbolAddress((void**)&Q, g_q);
    cudaGetSymbolAddress((void**)&K, g_k);
    cudaGetSymbolAddress((void**)&V, g_v);
    cudaGetSymbolAddress((void**)&Y, g_y);

    // 1) QKV GEMM + bias
    sgemm_bias_kernel<<<dim3(N_QKV / 128, ROWS / 128), 256>>>(
        x, Wqkv, bqkv, qkv, ROWS, N_QKV, CC);

    // 2) RoPE + head split
    rope_split_kernel<<<(BB * NHH * TT * HDD) / 256, 256>>>(qkv, Q, K, V);

    // 3) causal flash attention
    int smem = (2 * 64 * QK_LD + 2 * 64 * PV_LD) * (int)sizeof(float);  // 71680
    cudaFuncSetAttribute(flash_attn_kernel,
                         cudaFuncAttributeMaxDynamicSharedMemorySize, smem);
    flash_attn_kernel<<<dim3(TT / 64, BB * NHH), 256, smem>>>(Q, K, V, Y);

    // 4) output projection + bias
    sgemm_bias_kernel<<<dim3(CC / 128, ROWS / 128), 256>>>(
        Y, Wproj, bproj, out, ROWS, CC, CC);
}